// round 7
// baseline (speedup 1.0000x reference)
#include <cuda_runtime.h>
#include <math.h>

#define NG     128
#define NPER   512
#define NNODE  (NG*NPER)      // 65536
#define NEDGE  1048576
#define KTOP   30
#define DNODE  64
#define DEDGE  32
#define D0     96
#define DL     32
#define HSTRIDE 96            // hcat stride (ch96 handled in k_tail shared)
#define TOTALF 97
#define C1N    16
#define C2N    32
#define KW     5
#define PLEN   15
#define CONVL  11
#define DENSE  352
#define OUTD   128

// ---------------- scratch ----------------
__device__ float  g_zA [NNODE*DL];
__device__ float  g_zB [NNODE*DL];
__device__ float  g_z3 [NNODE];
__device__ float  g_hcat[NNODE*HSTRIDE];
__device__ float  g_degs[NNODE];
__device__ int    g_cnt [NNODE];
__device__ int    g_row [NNODE];
__device__ int    g_cur [NNODE];
__device__ int    g_bsum[64];
__device__ int2   g_pair[NEDGE];    // .x = src node, .y = edge id (dst-sorted)

__device__ __forceinline__ float* zsel(int s) { return s == 0 ? g_zA : g_zB; }

// ---------------- CSR build ----------------
__global__ void k_hist(const int* __restrict__ dst) {
    int i = blockIdx.x * 1024 + threadIdx.x;
    int4 d = ((const int4*)dst)[i];
    atomicAdd(&g_cnt[d.x], 1);
    atomicAdd(&g_cnt[d.y], 1);
    atomicAdd(&g_cnt[d.z], 1);
    atomicAdd(&g_cnt[d.w], 1);
}

__global__ void k_scanA() {
    __shared__ int s[1024];
    int i = blockIdx.x * 1024 + threadIdx.x;
    int v = g_cnt[i];
    s[threadIdx.x] = v; __syncthreads();
    for (int off = 1; off < 1024; off <<= 1) {
        int t = (threadIdx.x >= off) ? s[threadIdx.x - off] : 0;
        __syncthreads();
        s[threadIdx.x] += t;
        __syncthreads();
    }
    g_row[i] = s[threadIdx.x] - v;
    if (threadIdx.x == 1023) g_bsum[blockIdx.x] = s[1023];
}

__global__ void k_scanC() {
    __shared__ int sb[64];
    __shared__ int off;
    if (threadIdx.x < 64)
        sb[threadIdx.x] = (threadIdx.x < blockIdx.x) ? g_bsum[threadIdx.x] : 0;
    __syncthreads();
    if (threadIdx.x < 32) {
        int v = sb[threadIdx.x] + sb[threadIdx.x + 32];
#pragma unroll
        for (int o = 16; o > 0; o >>= 1) v += __shfl_down_sync(0xffffffffu, v, o);
        if (threadIdx.x == 0) off = v;
    }
    __syncthreads();
    int i = blockIdx.x * 1024 + threadIdx.x;
    int rs = g_row[i] + off;
    g_row[i] = rs;
    g_cur[i] = rs;
    g_degs[i] = (float)g_cnt[i] + 1.f;
}

__global__ void k_fill(const int* __restrict__ src, const int* __restrict__ dst) {
    int i = blockIdx.x * 1024 + threadIdx.x;
    int4 d = ((const int4*)dst)[i];
    int4 s = ((const int4*)src)[i];
    int e = i * 4;
    int p0 = atomicAdd(&g_cur[d.x], 1);
    g_pair[p0] = make_int2(s.x, e);
    int p1 = atomicAdd(&g_cur[d.y], 1);
    g_pair[p1] = make_int2(s.y, e + 1);
    int p2 = atomicAdd(&g_cur[d.z], 1);
    g_pair[p2] = make_int2(s.z, e + 2);
    int p3 = atomicAdd(&g_cur[d.w], 1);
    g_pair[p3] = make_int2(s.w, e + 3);
}

// quad-gather accumulate helper: 16 neighbors/iter, lane = q*8+r handles quads
// returns per-lane float4 partial; caller must xor-reduce over offsets 8,16.
__device__ __forceinline__ float4 quad_gather(const float4* __restrict__ base,
                                              int beg, int end, int use_eid,
                                              int q, int r, int lane) {
    float4 acc = make_float4(0.f, 0.f, 0.f, 0.f);
    for (int j = beg; j < end; j += 16) {
        int idx = -1;
        if (lane < 16 && j + lane < end)
            idx = use_eid ? g_pair[j + lane].y : g_pair[j + lane].x;
        int n1 = __shfl_sync(0xffffffffu, idx, q);
        int n2 = __shfl_sync(0xffffffffu, idx, q + 4);
        int n3 = __shfl_sync(0xffffffffu, idx, q + 8);
        int n4 = __shfl_sync(0xffffffffu, idx, q + 12);
        if (n1 >= 0) { float4 v = base[n1 * 8 + r]; acc.x += v.x; acc.y += v.y; acc.z += v.z; acc.w += v.w; }
        if (n2 >= 0) { float4 v = base[n2 * 8 + r]; acc.x += v.x; acc.y += v.y; acc.z += v.z; acc.w += v.w; }
        if (n3 >= 0) { float4 v = base[n3 * 8 + r]; acc.x += v.x; acc.y += v.y; acc.z += v.z; acc.w += v.w; }
        if (n4 >= 0) { float4 v = base[n4 * 8 + r]; acc.x += v.x; acc.y += v.y; acc.z += v.z; acc.w += v.w; }
    }
    return acc;
}

__device__ __forceinline__ void quad_reduce(float4& acc) {
#pragma unroll
    for (int off = 8; off < 32; off <<= 1) {
        acc.x += __shfl_xor_sync(0xffffffffu, acc.x, off);
        acc.y += __shfl_xor_sync(0xffffffffu, acc.y, off);
        acc.z += __shfl_xor_sync(0xffffffffu, acc.z, off);
        acc.w += __shfl_xor_sync(0xffffffffu, acc.w, off);
    }
}

// ---------------- build z0 = [nf | e2n] @ W0 ----------------
__global__ void k_build0(const float* __restrict__ nf, const float* __restrict__ ef,
                         const float* __restrict__ W0) {
    __shared__ float Ws[D0 * DL];
    __shared__ float agg[8][D0];
    int tid = threadIdx.x;
    for (int i = tid; i < D0 * DL; i += 256) Ws[i] = W0[i];
    __syncthreads();
    int w = tid >> 5, lane = tid & 31;
    int q = lane >> 3, r = lane & 7;
    int n = blockIdx.x * 8 + w;
    agg[w][lane]      = nf[n * DNODE + lane];
    agg[w][32 + lane] = nf[n * DNODE + 32 + lane];
    int beg = g_row[n], end = beg + g_cnt[n];
    float4 acc = quad_gather((const float4*)ef, beg, end, 1, q, r, lane);
    quad_reduce(acc);
    if (q == 0) ((float4*)(&agg[w][64]))[r] = acc;
    __syncwarp();
    float z = 0.f;
#pragma unroll
    for (int d = 0; d < D0; d++) z += agg[w][d] * Ws[d * DL + lane];
    g_zA[n * DL + lane] = z;
}

// ---------------- gather z + tanh + project to next z (32->32) ----------------
__global__ void k_gather32(int insel, int outsel, int hcat_off,
                           const float* __restrict__ b, const float* __restrict__ Wn) {
    __shared__ float Ws[DL * DL];
    __shared__ float bs[DL];
    __shared__ float aggs[8][DL];
    int tid = threadIdx.x;
    for (int i = tid; i < DL * DL; i += 256) Ws[i] = Wn[i];
    if (tid < DL) bs[tid] = b[tid];
    __syncthreads();
    int w = tid >> 5, lane = tid & 31;
    int q = lane >> 3, r = lane & 7;
    int n = blockIdx.x * 8 + w;
    const float4* z4 = (const float4*)zsel(insel);
    int beg = g_row[n], end = beg + g_cnt[n];
    float4 acc = quad_gather(z4, beg, end, 0, q, r, lane);
    if (q == 0) {               // own contribution, counted once
        float4 own = z4[n * 8 + r];
        acc.x += own.x; acc.y += own.y; acc.z += own.z; acc.w += own.w;
    }
    quad_reduce(acc);
    if (q == 0) ((float4*)aggs[w])[r] = acc;
    __syncwarp();
    float val = tanhf((aggs[w][lane] + bs[lane]) / g_degs[n]);
    g_hcat[n * HSTRIDE + hcat_off + lane] = val;
    __syncwarp();
    aggs[w][lane] = val;
    __syncwarp();
    float zn = 0.f;
#pragma unroll
    for (int d = 0; d < DL; d++) zn += aggs[w][d] * Ws[d * DL + lane];
    zsel(outsel)[n * DL + lane] = zn;
}

// ---------------- gather z + tanh + project to scalar (32->1) ----------------
__global__ void k_gather_p1(int insel, const float* __restrict__ b,
                            const float* __restrict__ W3) {
    __shared__ float aggs[8][DL];
    int tid = threadIdx.x;
    int w = tid >> 5, lane = tid & 31;
    int q = lane >> 3, r = lane & 7;
    int n = blockIdx.x * 8 + w;
    const float4* z4 = (const float4*)zsel(insel);
    int beg = g_row[n], end = beg + g_cnt[n];
    float4 acc = quad_gather(z4, beg, end, 0, q, r, lane);
    if (q == 0) {
        float4 own = z4[n * 8 + r];
        acc.x += own.x; acc.y += own.y; acc.z += own.z; acc.w += own.w;
    }
    quad_reduce(acc);
    if (q == 0) ((float4*)aggs[w])[r] = acc;
    __syncwarp();
    float val = tanhf((aggs[w][lane] + b[lane]) / g_degs[n]);
    g_hcat[n * HSTRIDE + 64 + lane] = val;
    float v = val * W3[lane];
#pragma unroll
    for (int off = 16; off > 0; off >>= 1) v += __shfl_xor_sync(0xffffffffu, v, off);
    if (lane == 0) g_z3[n] = v;
}

// ---------------- fused: ch96 gather + topk + head (one block per group) ----------------
__global__ void k_tail(const float* __restrict__ b3,
                       const float* __restrict__ cw1, const float* __restrict__ cb1,
                       const float* __restrict__ cw2, const float* __restrict__ cb2,
                       const float* __restrict__ ow,  const float* __restrict__ ob,
                       float* __restrict__ out) {
    __shared__ float ch96[NPER];
    __shared__ float v[NPER];
    __shared__ int   ix[NPER];
    __shared__ float pooled[KTOP][TOTALF];
    __shared__ float c1s[C1N][KTOP];
    __shared__ float c1p[C1N][PLEN];
    __shared__ float c2s[DENSE];
    int g = blockIdx.x, tid = threadIdx.x;      // 256 threads

    // ---- channel 96: scalar gather of z3 over neighbors ----
    float bb = b3[0];
#pragma unroll
    for (int half = 0; half < 2; half++) {
        int i = tid + half * 256;
        int n = g * NPER + i;
        float a = g_z3[n];
        int beg = g_row[n], end = beg + g_cnt[n];
        int j = beg;
        float a1 = 0.f, a2 = 0.f, a3 = 0.f;
        for (; j + 3 < end; j += 4) {
            a  += g_z3[g_pair[j].x];
            a1 += g_z3[g_pair[j+1].x];
            a2 += g_z3[g_pair[j+2].x];
            a3 += g_z3[g_pair[j+3].x];
        }
        for (; j < end; j++) a += g_z3[g_pair[j].x];
        a = (a + a1) + (a2 + a3);
        float cv = tanhf((a + bb) / g_degs[n]);
        ch96[i] = cv;
        v[i] = cv;
        ix[i] = i;
    }
    __syncthreads();

    // ---- bitonic top-K (value desc, index asc ties) ----
    for (int k = 2; k <= NPER; k <<= 1) {
        for (int j = k >> 1; j > 0; j >>= 1) {
            for (int i = tid; i < NPER; i += 256) {
                int p = i ^ j;
                if (p > i) {
                    float va = v[i], vb = v[p];
                    int ia = ix[i], ib = ix[p];
                    bool a_first = (va > vb) || (va == vb && ia < ib);
                    bool up = ((i & k) == 0);
                    if (up ? !a_first : a_first) {
                        v[i] = vb; v[p] = va;
                        ix[i] = ib; ix[p] = ia;
                    }
                }
            }
            __syncthreads();
        }
    }

    // ---- gather pooled (ch 0..95 from hcat, ch96 from shared) ----
    for (int t = tid; t < KTOP * HSTRIDE; t += 256) {
        int kk = t / HSTRIDE, d = t - kk * HSTRIDE;
        int node = g * NPER + ix[kk];
        pooled[kk][d] = g_hcat[node * HSTRIDE + d];
    }
    if (tid < KTOP) pooled[tid][96] = ch96[ix[tid]];
    __syncthreads();

    // ---- 1x1 conv + relu ----
    for (int t = tid; t < C1N * KTOP; t += 256) {
        int o = t / KTOP, kk = t - o * KTOP;
        float s = cb1[o];
#pragma unroll 8
        for (int d = 0; d < TOTALF; d++) s += pooled[kk][d] * cw1[o * TOTALF + d];
        c1s[o][kk] = fmaxf(s, 0.f);
    }
    __syncthreads();

    // ---- maxpool /2 ----
    for (int t = tid; t < C1N * PLEN; t += 256) {
        int o = t / PLEN, j = t - o * PLEN;
        c1p[o][j] = fmaxf(c1s[o][2 * j], c1s[o][2 * j + 1]);
    }
    __syncthreads();

    // ---- conv k=5 + relu ----
    for (int t = tid; t < C2N * CONVL; t += 256) {
        int o = t / CONVL, j = t - o * CONVL;
        float s = cb2[o];
#pragma unroll
        for (int i = 0; i < C1N; i++)
#pragma unroll
            for (int u = 0; u < KW; u++)
                s += c1p[i][j + u] * cw2[(o * C1N + i) * KW + u];
        c2s[o * CONVL + j] = fmaxf(s, 0.f);
    }
    __syncthreads();

    // ---- dense 352->128 + relu ----
    if (tid < OUTD) {
        int u = tid;
        float s = ob[u];
#pragma unroll 8
        for (int f = 0; f < DENSE; f++) s += c2s[f] * ow[f * OUTD + u];
        out[g * OUTD + u] = fmaxf(s, 0.f);
    }
}

// ---------------- launch ----------------
extern "C" void kernel_launch(void* const* d_in, const int* in_sizes, int n_in,
                              void* d_out, int out_size) {
    const float* node_feat = (const float*)d_in[0];
    const float* edge_feat = (const float*)d_in[1];
    const int*   edge_src  = (const int*)  d_in[2];
    const int*   edge_dst  = (const int*)  d_in[3];
    const float* W0 = (const float*)d_in[4];
    const float* b0 = (const float*)d_in[5];
    const float* W1 = (const float*)d_in[6];
    const float* b1 = (const float*)d_in[7];
    const float* W2 = (const float*)d_in[8];
    const float* b2 = (const float*)d_in[9];
    const float* W3 = (const float*)d_in[10];
    const float* b3 = (const float*)d_in[11];
    const float* cw1 = (const float*)d_in[12];
    const float* cb1 = (const float*)d_in[13];
    const float* cw2 = (const float*)d_in[14];
    const float* cb2 = (const float*)d_in[15];
    const float* ow  = (const float*)d_in[16];
    const float* ob  = (const float*)d_in[17];
    float* out = (float*)d_out;

    void* cnt_ptr = nullptr;
    cudaGetSymbolAddress(&cnt_ptr, g_cnt);
    cudaMemsetAsync(cnt_ptr, 0, NNODE * sizeof(int), 0);

    k_hist <<<NEDGE / 4096, 1024>>>(edge_dst);
    k_scanA<<<64, 1024>>>();
    k_scanC<<<64, 1024>>>();
    k_fill <<<NEDGE / 4096, 1024>>>(edge_src, edge_dst);

    k_build0   <<<NNODE / 8, 256>>>(node_feat, edge_feat, W0);  // -> zA
    k_gather32 <<<NNODE / 8, 256>>>(0, 1, 0,  b0, W1);          // zA -> hcat0, zB
    k_gather32 <<<NNODE / 8, 256>>>(1, 0, 32, b1, W2);          // zB -> hcat32, zA
    k_gather_p1<<<NNODE / 8, 256>>>(0, b2, W3);                 // zA -> hcat64, z3

    k_tail<<<NG, 256>>>(b3, cw1, cb1, cw2, cb2, ow, ob, out);
}